// round 3
// baseline (speedup 1.0000x reference)
#include <cuda_runtime.h>

// IndRNN recurrence: h_t = relu(h_{t-1} * w_hh + x_t), elementwise over
// 32*1024 = 32768 independent channels, 2048 timesteps.
// Pure streaming: 256 MB in + 256 MB out -> HBM-bound, floor ~64 us @ 8 TB/s.
//
// One thread per channel (lane-adjacent channels -> coalesced 128B
// warp-loads). The recurrence is serial in t (FFMA -> FMNMX) but x[t]
// loads are independent of h, so we ping-pong two register buffers of
// UNROLL timesteps: while the serial chain drains buffer A, buffer B's
// UNROLL independent loads are in flight (covering DRAM latency).

constexpr int LEN    = 2048;
constexpr int BATCH  = 32;
constexpr int HIDDEN = 1024;
constexpr int NCH    = BATCH * HIDDEN;   // 32768 channels
constexpr int UNROLL = 16;               // timesteps per buffer half
static_assert(LEN % (2 * UNROLL) == 0, "ping-pong needs even group count");

__global__ void __launch_bounds__(128, 16)
indrnn_kernel(const float* __restrict__ x,
              const float* __restrict__ w_hh,
              const float* __restrict__ h0,
              float* __restrict__ out)
{
    const int ch = blockIdx.x * blockDim.x + threadIdx.x;   // exact coverage

    const float w = __ldg(&w_hh[ch & (HIDDEN - 1)]);
    float h = h0[ch];

    const float* xp = x + ch;
    float*       op = out + ch;

    float bufA[UNROLL];
    float bufB[UNROLL];

    // Prime buffer A with timesteps [0, UNROLL). Streaming loads: x is
    // touch-once (256 MB > L2), evict-first.
    #pragma unroll
    for (int i = 0; i < UNROLL; ++i)
        bufA[i] = __ldcs(xp + (size_t)i * NCH);

    // Each iteration handles 2*UNROLL timesteps: fill B while draining A,
    // then fill A (next iter's) while draining B. No register copies.
    #pragma unroll 1
    for (int t0 = 0; t0 < LEN; t0 += 2 * UNROLL) {
        // Fill B: timesteps [t0+UNROLL, t0+2*UNROLL)
        #pragma unroll
        for (int i = 0; i < UNROLL; ++i)
            bufB[i] = __ldcs(xp + (size_t)(t0 + UNROLL + i) * NCH);

        // Drain A: timesteps [t0, t0+UNROLL)
        #pragma unroll
        for (int i = 0; i < UNROLL; ++i) {
            h = fmaxf(fmaf(h, w, bufA[i]), 0.0f);
            __stcs(op + (size_t)(t0 + i) * NCH, h);
        }

        // Fill A for the next iteration: timesteps [t0+2*UNROLL, t0+3*UNROLL)
        const int tn = t0 + 2 * UNROLL;
        if (tn < LEN) {
            #pragma unroll
            for (int i = 0; i < UNROLL; ++i)
                bufA[i] = __ldcs(xp + (size_t)(tn + i) * NCH);
        }

        // Drain B: timesteps [t0+UNROLL, t0+2*UNROLL)
        #pragma unroll
        for (int i = 0; i < UNROLL; ++i) {
            h = fmaxf(fmaf(h, w, bufB[i]), 0.0f);
            __stcs(op + (size_t)(t0 + UNROLL + i) * NCH, h);
        }
    }
}

extern "C" void kernel_launch(void* const* d_in, const int* in_sizes, int n_in,
                              void* d_out, int out_size)
{
    const float* x    = (const float*)d_in[0];   // [LEN, BATCH, HIDDEN]
    const float* w_hh = (const float*)d_in[1];   // [HIDDEN]
    const float* h0   = (const float*)d_in[2];   // [BATCH, HIDDEN]
    float*       out  = (float*)d_out;           // [LEN, BATCH, HIDDEN]

    const int threads = 128;
    const int blocks  = NCH / threads;           // 256 blocks
    indrnn_kernel<<<blocks, threads>>>(x, w_hh, h0, out);
}

// round 4
// speedup vs baseline: 3.2900x; 3.2900x over previous
#include <cuda_runtime.h>

// IndRNN recurrence: h_t = relu(h_{t-1} * w_hh + x_t), elementwise over
// 32*1024 = 32768 independent channels, 2048 timesteps.
// Pure streaming: 256 MB in + 256 MB out -> HBM-bound, floor ~64 us @ 8 TB/s.
//
// One thread per channel (lane-adjacent channels -> coalesced 128B
// warp-loads). The recurrence is serial in t (FFMA -> FMNMX) but x[t]
// loads are independent of h. Ping-pong two register buffers of UNROLL
// timesteps so ~20 independent loads/thread are in flight while the
// serial chain drains the other buffer.
//
// R3 lesson: __launch_bounds__(128,16) capped regs at 32 and destroyed
// the register double-buffer (DRAM 16.5%, 370us). Occupancy is
// problem-size-bound (1024 warps total, ~7/SM) so the cap bought nothing.
// Chip needs ~2.4 MB in flight for 8 TB/s -> ~18+ floats/thread -> UNROLL=20.

constexpr int LEN    = 2048;
constexpr int BATCH  = 32;
constexpr int HIDDEN = 1024;
constexpr int NCH    = BATCH * HIDDEN;   // 32768 channels
constexpr int UNROLL = 20;               // timesteps per buffer half
static_assert(LEN % (2 * UNROLL) == 8 || LEN % (2 * UNROLL) == 0 || true, "");

__global__ void __launch_bounds__(128)
indrnn_kernel(const float* __restrict__ x,
              const float* __restrict__ w_hh,
              const float* __restrict__ h0,
              float* __restrict__ out)
{
    const int ch = blockIdx.x * blockDim.x + threadIdx.x;   // exact coverage

    const float w = __ldg(&w_hh[ch & (HIDDEN - 1)]);
    float h = h0[ch];

    const float* xp = x + ch;
    float*       op = out + ch;

    float bufA[UNROLL];
    float bufB[UNROLL];

    // Prime buffer A with timesteps [0, UNROLL). Streaming loads: x is
    // touch-once (256 MB > L2), evict-first.
    #pragma unroll
    for (int i = 0; i < UNROLL; ++i)
        bufA[i] = __ldcs(xp + (size_t)i * NCH);

    // Each iteration handles 2*UNROLL timesteps: fill B while draining A,
    // then refill A while draining B. LEN=2048, 2*UNROLL=40 -> 51 full
    // iterations cover 2040 steps; tail of 8 handled after the loop.
    constexpr int MAIN = (LEN / (2 * UNROLL)) * (2 * UNROLL);   // 2040

    #pragma unroll 1
    for (int t0 = 0; t0 < MAIN; t0 += 2 * UNROLL) {
        // Fill B: timesteps [t0+UNROLL, t0+2*UNROLL)
        #pragma unroll
        for (int i = 0; i < UNROLL; ++i)
            bufB[i] = __ldcs(xp + (size_t)(t0 + UNROLL + i) * NCH);

        // Drain A
        #pragma unroll
        for (int i = 0; i < UNROLL; ++i) {
            h = fmaxf(fmaf(h, w, bufA[i]), 0.0f);
            __stcs(op + (size_t)(t0 + i) * NCH, h);
        }

        // Fill A for next iteration (or tail): timesteps [t0+2U, t0+3U)
        const int tn = t0 + 2 * UNROLL;
        #pragma unroll
        for (int i = 0; i < UNROLL; ++i)
            if (tn + i < LEN)
                bufA[i] = __ldcs(xp + (size_t)(tn + i) * NCH);

        // Drain B
        #pragma unroll
        for (int i = 0; i < UNROLL; ++i) {
            h = fmaxf(fmaf(h, w, bufB[i]), 0.0f);
            __stcs(op + (size_t)(t0 + UNROLL + i) * NCH, h);
        }
    }

    // Tail: timesteps [MAIN, LEN) already loaded into bufA by the last fill.
    #pragma unroll
    for (int i = 0; i < LEN - MAIN; ++i) {
        h = fmaxf(fmaf(h, w, bufA[i]), 0.0f);
        __stcs(op + (size_t)(MAIN + i) * NCH, h);
    }
}

extern "C" void kernel_launch(void* const* d_in, const int* in_sizes, int n_in,
                              void* d_out, int out_size)
{
    const float* x    = (const float*)d_in[0];   // [LEN, BATCH, HIDDEN]
    const float* w_hh = (const float*)d_in[1];   // [HIDDEN]
    const float* h0   = (const float*)d_in[2];   // [BATCH, HIDDEN]
    float*       out  = (float*)d_out;           // [LEN, BATCH, HIDDEN]

    const int threads = 128;
    const int blocks  = NCH / threads;           // 256 blocks
    indrnn_kernel<<<blocks, threads>>>(x, w_hh, h0, out);
}

// round 5
// speedup vs baseline: 3.6939x; 1.1228x over previous
#include <cuda_runtime.h>

// IndRNN recurrence: h_t = relu(h_{t-1} * w_hh + x_t), elementwise over
// 32*1024 = 32768 independent channels, 2048 timesteps.
// Pure streaming: 256 MB in + 256 MB out -> HBM-bound, floor ~64 us @ 8 TB/s.
//
// One thread per channel (lane-adjacent -> coalesced 128B warp-loads).
// Recurrence serial in t; x[t] loads independent of h -> register
// ping-pong of UNROLL timesteps keeps ~32 loads/thread in flight.
//
// History:
//  R3: __launch_bounds__(128,16) capped regs=32, killed MLP -> 370us, DRAM 16%.
//  R4: cap removed, UNROLL=20, regs=56 -> 112.7us, DRAM 54%, issue 9%.
//      Little's law: 2.6MB in flight / 4.45TB/s -> ~590ns loaded latency.
//      BW scales with in-flight bytes -> raise UNROLL.
//  R5: UNROLL=32 -> 4.2MB in flight; 2048 % 64 == 0 so no tail/predicates.

constexpr int LEN    = 2048;
constexpr int BATCH  = 32;
constexpr int HIDDEN = 1024;
constexpr int NCH    = BATCH * HIDDEN;   // 32768 channels
constexpr int UNROLL = 32;               // timesteps per buffer half
static_assert(LEN % (2 * UNROLL) == 0, "exact tiling, no tail");

__global__ void __launch_bounds__(128)
indrnn_kernel(const float* __restrict__ x,
              const float* __restrict__ w_hh,
              const float* __restrict__ h0,
              float* __restrict__ out)
{
    const int ch = blockIdx.x * blockDim.x + threadIdx.x;   // exact coverage

    const float w = __ldg(&w_hh[ch & (HIDDEN - 1)]);
    float h = h0[ch];

    const float* xp = x + ch;
    float*       op = out + ch;

    float bufA[UNROLL];
    float bufB[UNROLL];

    // Prime buffer A with timesteps [0, UNROLL). Streaming loads: x is
    // touch-once (256 MB > L2), evict-first.
    #pragma unroll
    for (int i = 0; i < UNROLL; ++i)
        bufA[i] = __ldcs(xp + (size_t)i * NCH);

    // 2*UNROLL = 64 timesteps per iteration, 32 iterations exactly.
    #pragma unroll 1
    for (int t0 = 0; t0 < LEN; t0 += 2 * UNROLL) {
        // Fill B: timesteps [t0+UNROLL, t0+2*UNROLL)
        #pragma unroll
        for (int i = 0; i < UNROLL; ++i)
            bufB[i] = __ldcs(xp + (size_t)(t0 + UNROLL + i) * NCH);

        // Drain A: serial chain over [t0, t0+UNROLL)
        #pragma unroll
        for (int i = 0; i < UNROLL; ++i) {
            h = fmaxf(fmaf(h, w, bufA[i]), 0.0f);
            __stcs(op + (size_t)(t0 + i) * NCH, h);
        }

        // Refill A for the next iteration: [t0+2U, t0+3U). On the last
        // iteration tn == LEN and the whole fill drops out (uniform branch).
        const int tn = t0 + 2 * UNROLL;
        if (tn < LEN) {
            #pragma unroll
            for (int i = 0; i < UNROLL; ++i)
                bufA[i] = __ldcs(xp + (size_t)(tn + i) * NCH);
        }

        // Drain B: [t0+UNROLL, t0+2*UNROLL)
        #pragma unroll
        for (int i = 0; i < UNROLL; ++i) {
            h = fmaxf(fmaf(h, w, bufB[i]), 0.0f);
            __stcs(op + (size_t)(t0 + UNROLL + i) * NCH, h);
        }
    }
}

extern "C" void kernel_launch(void* const* d_in, const int* in_sizes, int n_in,
                              void* d_out, int out_size)
{
    const float* x    = (const float*)d_in[0];   // [LEN, BATCH, HIDDEN]
    const float* w_hh = (const float*)d_in[1];   // [HIDDEN]
    const float* h0   = (const float*)d_in[2];   // [BATCH, HIDDEN]
    float*       out  = (float*)d_out;           // [LEN, BATCH, HIDDEN]

    const int threads = 128;
    const int blocks  = NCH / threads;           // 256 blocks
    indrnn_kernel<<<blocks, threads>>>(x, w_hh, h0, out);
}